// round 10
// baseline (speedup 1.0000x reference)
#include <cuda_runtime.h>
#include <cuda_fp16.h>
#include <cstdint>

// Problem constants
#define MT     32768
#define DIN    1024
#define DB     256
#define KC     16384
#define NSPLIT 4
#define CODES_PER_SPLIT (KC / NSPLIT)   // 4096
#define NT_CTA (CODES_PER_SPLIT / 128)  // 32 tiles of 128 codes

#define LDA    264                       // padded f16 row stride (528 B)
#define A_BYTES  (128 * LDA * 2)         // 67584 (A panel, 128 rows)
#define BM_BYTES (96 * LDA * 2)          // 50688 (mma B: 96 code rows)
#define BH_BYTES 16384                   // hfma B: 32 codes x 512 B (swizzled)
#define OFF_BM(b) (A_BYTES + (b) * BM_BYTES)
#define OFF_BH(b) (A_BYTES + 2 * BM_BYTES + (b) * BH_BYTES)
#define SMEM_ARG  (A_BYTES + 2 * BM_BYTES + 2 * BH_BYTES)   // 201728

// xhat staged layout
#define LDS2      272
#define STAGE_B   (128 * LDS2)           // 34816
#define SMEM_XHAT (4 * STAGE_B)          // 139264

// Scratch (__device__ globals; no allocation allowed)
__device__ float  g_halfnorm[KC];
__device__ int    g_cand[MT * 16];
__device__ __half g_zh[(size_t)MT * DB];
__device__ __half g_eh[(size_t)KC * DB];
__device__ __half g_rzh[(size_t)MT * DB];
__device__ __half g_wouth[(size_t)DIN * DB];

// ======================= PTX helpers (baseline sm_80+) =====================
__device__ __forceinline__ uint32_t smem_to_u32(const void* p) {
    uint32_t a;
    asm("{ .reg .u64 t; cvta.to.shared.u64 t, %1; cvt.u32.u64 %0, t; }"
        : "=r"(a) : "l"(p));
    return a;
}
__device__ __forceinline__ void ldsm_x4(uint32_t* r, uint32_t addr) {
    asm volatile("ldmatrix.sync.aligned.m8n8.x4.shared.b16 {%0,%1,%2,%3}, [%4];"
                 : "=r"(r[0]), "=r"(r[1]), "=r"(r[2]), "=r"(r[3]) : "r"(addr));
}
__device__ __forceinline__ void lds128(uint4& v, uint32_t addr) {
    asm volatile("ld.shared.v4.u32 {%0,%1,%2,%3}, [%4];"
                 : "=r"(v.x), "=r"(v.y), "=r"(v.z), "=r"(v.w) : "r"(addr));
}
__device__ __forceinline__ void mma16816_h(uint32_t* c, const uint32_t* a,
                                           const uint32_t* b) {
    asm volatile(
        "mma.sync.aligned.m16n8k16.row.col.f16.f16.f16.f16 "
        "{%0,%1}, {%2,%3,%4,%5}, {%6,%7}, {%0,%1};"
        : "+r"(c[0]), "+r"(c[1])
        : "r"(a[0]), "r"(a[1]), "r"(a[2]), "r"(a[3]), "r"(b[0]), "r"(b[1]));
}
__device__ __forceinline__ void mma16816_f(float* c, const uint32_t* a,
                                           const uint32_t* b) {
    asm volatile(
        "mma.sync.aligned.m16n8k16.row.col.f32.f16.f16.f32 "
        "{%0,%1,%2,%3}, {%4,%5,%6,%7}, {%8,%9}, {%0,%1,%2,%3};"
        : "+f"(c[0]), "+f"(c[1]), "+f"(c[2]), "+f"(c[3])
        : "r"(a[0]), "r"(a[1]), "r"(a[2]), "r"(a[3]), "r"(b[0]), "r"(b[1]));
}
#define CP_ASYNC16(dst, src) \
    asm volatile("cp.async.cg.shared.global [%0], [%1], 16;" :: "r"(dst), "l"(src))
#define CP_COMMIT()  asm volatile("cp.async.commit_group;" ::: "memory")
#define CP_WAIT(n)   asm volatile("cp.async.wait_group %0;" :: "n"(n) : "memory")

__device__ __forceinline__ uint32_t pack2h(float a, float b)
{
    return ((uint32_t)__half_as_ushort(__float2half_rn(b)) << 16) |
           (uint32_t)__half_as_ushort(__float2half_rn(a));
}

// ---------------------------------------------------------------------------
// fp32 GEMM with bias, register-buffered K pipeline, optional fp16 mirror.
// ---------------------------------------------------------------------------
__global__ __launch_bounds__(256, 2) void gemm_bias_kernel(
    const float* __restrict__ A, const float* __restrict__ B,
    const float* __restrict__ bias, float* __restrict__ C,
    __half* __restrict__ Ch, int Kd, int N)
{
    __shared__ float As[8][128];
    __shared__ float Bs[8][128];
    const int rowBase = blockIdx.y * 128;
    const int colBase = blockIdx.x * 128;
    const int tid = threadIdx.x;
    const int ty = tid >> 4, tx = tid & 15;

    float acc[8][8];
#pragma unroll
    for (int i = 0; i < 8; i++)
#pragma unroll
        for (int j = 0; j < 8; j++) acc[i][j] = 0.f;

    const int ar = tid >> 1, ac4 = (tid & 1) * 4;
    const int br = tid >> 5, bc = (tid & 31) * 4;
    const float* Aptr = A + (size_t)(rowBase + ar) * Kd + ac4;
    const float* Bptr = B + (size_t)br * N + colBase + bc;

    float4 av = *(const float4*)(Aptr);
    float4 bv = *(const float4*)(Bptr);

    for (int kt = 0; kt < Kd; kt += 8) {
        As[ac4 + 0][ar] = av.x; As[ac4 + 1][ar] = av.y;
        As[ac4 + 2][ar] = av.z; As[ac4 + 3][ar] = av.w;
        *(float4*)(&Bs[br][bc]) = bv;
        __syncthreads();
        if (kt + 8 < Kd) {
            av = *(const float4*)(Aptr + kt + 8);
            bv = *(const float4*)(Bptr + (size_t)(kt + 8) * N);
        }
#pragma unroll
        for (int k = 0; k < 8; k++) {
            float4 a0 = *(const float4*)(&As[k][ty * 8]);
            float4 a1 = *(const float4*)(&As[k][ty * 8 + 4]);
            float4 b0 = *(const float4*)(&Bs[k][tx * 8]);
            float4 b1 = *(const float4*)(&Bs[k][tx * 8 + 4]);
            float ra[8] = {a0.x, a0.y, a0.z, a0.w, a1.x, a1.y, a1.z, a1.w};
            float rb[8] = {b0.x, b0.y, b0.z, b0.w, b1.x, b1.y, b1.z, b1.w};
#pragma unroll
            for (int i = 0; i < 8; i++)
#pragma unroll
                for (int j = 0; j < 8; j++) acc[i][j] += ra[i] * rb[j];
        }
        __syncthreads();
    }
#pragma unroll
    for (int i = 0; i < 8; i++) {
        int row = rowBase + ty * 8 + i;
#pragma unroll
        for (int j = 0; j < 8; j += 4) {
            int col = colBase + tx * 8 + j;
            float4 o;
            o.x = acc[i][j + 0] + __ldg(bias + col + 0);
            o.y = acc[i][j + 1] + __ldg(bias + col + 1);
            o.z = acc[i][j + 2] + __ldg(bias + col + 2);
            o.w = acc[i][j + 3] + __ldg(bias + col + 3);
            *(float4*)(C + (size_t)row * N + col) = o;
            if (Ch) {
                uint2 h;
                h.x = pack2h(o.x, o.y);
                h.y = pack2h(o.z, o.w);
                *(uint2*)(Ch + (size_t)row * N + col) = h;
            }
        }
    }
}

// ---------------------------------------------------------------------------
__global__ void halfnorm_kernel(const float* __restrict__ E)
{
    int row = blockIdx.x * 8 + (threadIdx.x >> 5);
    int lane = threadIdx.x & 31;
    const float* e = E + (size_t)row * DB;
    float s = 0.f;
#pragma unroll
    for (int c = lane; c < DB; c += 32) { float v = e[c]; s += v * v; }
#pragma unroll
    for (int off = 16; off > 0; off >>= 1) s += __shfl_xor_sync(0xffffffffu, s, off);
    if (lane == 0) g_halfnorm[row] = 0.5f * s;
}

__global__ void convert_wout_kernel(const float* __restrict__ W)
{
    int idx = blockIdx.x * 256 + threadIdx.x;
    int k = idx >> 10, n = idx & 1023;
    g_wouth[(size_t)n * DB + k] = __float2half_rn(W[idx]);
}

// ---------------------------------------------------------------------------
// Hybrid argmin: 12 HMMA warps (codes 0-95/tile) + 4 HFMA2 warps (codes
// 96-127/tile, rows via LDG, codes via XOR-swizzled smem).
// Grid (MT/128, NSPLIT), 512 threads.
// ---------------------------------------------------------------------------
__global__ __launch_bounds__(512, 1) void argmin_mma_kernel()
{
    extern __shared__ char smem[];
    const uint32_t sbase = smem_to_u32(smem);

    const int tid  = threadIdx.x;
    const int lane = tid & 31;
    const int wid  = tid >> 5;
    const int m0 = blockIdx.x * 128;
    const int codeBase = blockIdx.y * CODES_PER_SPLIT;

    // mma roles (wid 0..11): 4M x 3N, warp tile 32x32
    const int wm = wid & 3;
    const int wn = wid >> 2;            // 0..2 for mma warps
    const int warpM = wm * 32;
    const int warpN = wn * 32;
    const int tg2 = (lane & 3) * 2;
    // hfma roles (wid 12..15): warp owns 32 rows; lane = 8 rowsets x 4 codesets
    const int hw = wid - 12;
    const int rs = lane >> 2;           // 0..7 -> 4 rows each
    const int cs = lane & 3;            // 0..3 -> 8 codes each
    const uint32_t swz = (uint32_t)(cs << 1);

    // ---- A panel -> smem (for ldmatrix) ----
#pragma unroll
    for (int i = 0; i < 8; i++) {
        int ch = tid + i * 512;
        int row = ch >> 5, c = ch & 31;
        uint4 v = *(const uint4*)(g_zh + (size_t)(m0 + row) * DB + c * 8);
        *(uint4*)(smem + row * (LDA * 2) + c * 16) = v;
    }

    // ---- prologue: B tile 0 (both regions) ----
    {
        const __half* sf = g_eh + (size_t)codeBase * DB;
#pragma unroll
        for (int i = 0; i < 6; i++) {
            int ch = tid + i * 512;          // 0..3071: 96 rows x 32 chunks
            int row = ch >> 5, c = ch & 31;
            CP_ASYNC16(sbase + OFF_BM(0) + row * (LDA * 2) + c * 16,
                       (const void*)(sf + (size_t)row * DB + c * 8));
        }
#pragma unroll
        for (int i = 0; i < 2; i++) {
            int ch = tid + i * 512;          // 0..1023: 32 codes x 32 chunks
            int code = ch >> 5, k8 = ch & 31;
            uint32_t dst = sbase + OFF_BH(0) + code * 512 +
                           ((uint32_t)(k8 ^ ((code >> 3) << 1)) & 31u) * 16u;
            CP_ASYNC16(dst, (const void*)(sf + (size_t)(96 + code) * DB + k8 * 8));
        }
        CP_COMMIT();
    }

    float b1v[4], b2v[4];
    int   b1i[4], b2i[4];
#pragma unroll
    for (int s = 0; s < 4; s++) {
        b1v[s] = -3.4e38f; b2v[s] = -3.4e38f; b1i[s] = 0; b2i[s] = 0;
    }

    for (int t = 0; t < NT_CTA; t++) {
        const int buf = t & 1;
        if (t + 1 < NT_CTA) {
            const int nb = buf ^ 1;
            const __half* sf = g_eh + (size_t)(codeBase + (t + 1) * 128) * DB;
#pragma unroll
            for (int i = 0; i < 6; i++) {
                int ch = tid + i * 512;
                int row = ch >> 5, c = ch & 31;
                CP_ASYNC16(sbase + OFF_BM(nb) + row * (LDA * 2) + c * 16,
                           (const void*)(sf + (size_t)row * DB + c * 8));
            }
#pragma unroll
            for (int i = 0; i < 2; i++) {
                int ch = tid + i * 512;
                int code = ch >> 5, k8 = ch & 31;
                uint32_t dst = sbase + OFF_BH(nb) + code * 512 +
                               ((uint32_t)(k8 ^ ((code >> 3) << 1)) & 31u) * 16u;
                CP_ASYNC16(dst, (const void*)(sf + (size_t)(96 + code) * DB + k8 * 8));
            }
            CP_COMMIT();
            CP_WAIT(1);
        } else {
            CP_WAIT(0);
        }
        __syncthreads();

        if (wid < 12) {
            // ============== HMMA: codes [tb, tb+96), f16 accumulate ========
            const uint32_t sA = sbase;
            const uint32_t sB = sbase + OFF_BM(buf);
            uint32_t acc[2][4][2];
#pragma unroll
            for (int mi = 0; mi < 2; mi++)
#pragma unroll
                for (int ni = 0; ni < 4; ni++) { acc[mi][ni][0] = 0u; acc[mi][ni][1] = 0u; }
#pragma unroll
            for (int k = 0; k < 16; k++) {
                uint32_t af[2][4], bfr[2][4];
#pragma unroll
                for (int mi = 0; mi < 2; mi++) {
                    int row = warpM + mi * 16 + (lane & 15);
                    int col = k * 16 + ((lane >> 4) << 3);
                    ldsm_x4(af[mi], sA + row * (LDA * 2) + col * 2);
                }
#pragma unroll
                for (int ni2 = 0; ni2 < 2; ni2++) {
                    int row = warpN + ni2 * 16 + (lane & 7) + (((lane >> 4) & 1) << 3);
                    int col = k * 16 + (((lane >> 3) & 1) << 3);
                    ldsm_x4(bfr[ni2], sB + row * (LDA * 2) + col * 2);
                }
#pragma unroll
                for (int mi = 0; mi < 2; mi++)
#pragma unroll
                    for (int ni = 0; ni < 4; ni++)
                        mma16816_h(acc[mi][ni], af[mi], &bfr[ni >> 1][(ni & 1) * 2]);
            }
            // fold (registers only)
            const int nb2 = codeBase + t * 128 + warpN;
            float hn[4][2];
#pragma unroll
            for (int ni = 0; ni < 4; ni++) {
                int code = nb2 + ni * 8 + tg2;
                hn[ni][0] = __ldg(&g_halfnorm[code]);
                hn[ni][1] = __ldg(&g_halfnorm[code + 1]);
            }
#pragma unroll
            for (int mi = 0; mi < 2; mi++) {
#pragma unroll
                for (int h = 0; h < 2; h++) {
                    const int s = mi * 2 + h;
                    float vv[8];
#pragma unroll
                    for (int ni = 0; ni < 4; ni++) {
                        float2 f = __half22float2(*(__half2*)&acc[mi][ni][h]);
                        vv[ni * 2 + 0] = f.x - hn[ni][0];
                        vv[ni * 2 + 1] = f.y - hn[ni][1];
                    }
                    float m01 = fmaxf(vv[0], vv[1]), m23 = fmaxf(vv[2], vv[3]);
                    float m45 = fmaxf(vv[4], vv[5]), m67 = fmaxf(vv[6], vv[7]);
                    float mx = fmaxf(fmaxf(m01, m23), fmaxf(m45, m67));
                    if (mx > b2v[s]) {
#pragma unroll
                        for (int e = 0; e < 8; e++) {
                            float v = vv[e];
                            int code = nb2 + (e >> 1) * 8 + tg2 + (e & 1);
                            if (v > b1v[s]) {
                                b2v[s] = b1v[s]; b2i[s] = b1i[s];
                                b1v[s] = v;      b1i[s] = code;
                            } else if (v > b2v[s]) {
                                b2v[s] = v; b2i[s] = code;
                            }
                        }
                    }
                }
            }
        } else {
            // ============== HFMA2: codes [tb+96, tb+128) ===================
            const uint32_t sBH = sbase + OFF_BH(buf);
            const int rowG = m0 + hw * 32 + rs * 4;
            __half2 acc[4][8];
#pragma unroll
            for (int r = 0; r < 4; r++)
#pragma unroll
                for (int j = 0; j < 8; j++) acc[r][j] = __float2half2_rn(0.f);

            for (int k8 = 0; k8 < 32; k8++) {
                uint4 a4[4];
#pragma unroll
                for (int r = 0; r < 4; r++)
                    a4[r] = __ldg((const uint4*)(g_zh + (size_t)(rowG + r) * DB) + k8);
                const uint32_t koff = ((uint32_t)k8 ^ swz) * 16u;
#pragma unroll
                for (int jh = 0; jh < 2; jh++) {
                    uint4 b4[4];
#pragma unroll
                    for (int jj = 0; jj < 4; jj++) {
                        int code = cs * 8 + jh * 4 + jj;
                        lds128(b4[jj], sBH + code * 512 + koff);
                    }
#pragma unroll
                    for (int r = 0; r < 4; r++) {
                        const __half2* ah = reinterpret_cast<const __half2*>(&a4[r]);
#pragma unroll
                        for (int jj = 0; jj < 4; jj++) {
                            const __half2* bh = reinterpret_cast<const __half2*>(&b4[jj]);
                            __half2 s = acc[r][jh * 4 + jj];
                            s = __hfma2(ah[0], bh[0], s);
                            s = __hfma2(ah[1], bh[1], s);
                            s = __hfma2(ah[2], bh[2], s);
                            s = __hfma2(ah[3], bh[3], s);
                            acc[r][jh * 4 + jj] = s;
                        }
                    }
                }
            }
            // fold (registers only)
            const int cb = codeBase + t * 128 + 96 + cs * 8;
            float hn[8];
#pragma unroll
            for (int j = 0; j < 8; j++) hn[j] = __ldg(&g_halfnorm[cb + j]);
#pragma unroll
            for (int r = 0; r < 4; r++) {
                float vv[8];
#pragma unroll
                for (int j = 0; j < 8; j++) {
                    float2 f = __half22float2(acc[r][j]);
                    vv[j] = f.x + f.y - hn[j];
                }
                float m01 = fmaxf(vv[0], vv[1]), m23 = fmaxf(vv[2], vv[3]);
                float m45 = fmaxf(vv[4], vv[5]), m67 = fmaxf(vv[6], vv[7]);
                float mx = fmaxf(fmaxf(m01, m23), fmaxf(m45, m67));
                if (mx > b2v[r]) {
#pragma unroll
                    for (int j = 0; j < 8; j++) {
                        float v = vv[j];
                        int code = cb + j;
                        if (v > b1v[r]) {
                            b2v[r] = b1v[r]; b2i[r] = b1i[r];
                            b1v[r] = v;      b1i[r] = code;
                        } else if (v > b2v[r]) {
                            b2v[r] = v; b2i[r] = code;
                        }
                    }
                }
            }
        }
        __syncthreads();
    }

    // ---- per-CTA reduction: 32 entries/row -> top-4 codes ----
    float* sv = (float*)smem;
    int*   si = (int*)(smem + 16384);
    if (wid < 12) {
#pragma unroll
        for (int s = 0; s < 4; s++) {
            int row = warpM + (s >> 1) * 16 + (s & 1) * 8 + (lane >> 2);
            int e = wn * 8 + (lane & 3) * 2;
            sv[row * 32 + e]     = b1v[s]; si[row * 32 + e]     = b1i[s];
            sv[row * 32 + e + 1] = b2v[s]; si[row * 32 + e + 1] = b2i[s];
        }
    } else {
#pragma unroll
        for (int r = 0; r < 4; r++) {
            int row = hw * 32 + rs * 4 + r;
            int e = 24 + cs * 2;
            sv[row * 32 + e]     = b1v[r]; si[row * 32 + e]     = b1i[r];
            sv[row * 32 + e + 1] = b2v[r]; si[row * 32 + e + 1] = b2i[r];
        }
    }
    __syncthreads();
    if (tid < 128) {
        float v4[4] = {-3.4e38f, -3.4e38f, -3.4e38f, -3.4e38f};
        int   i4[4] = {0x7fffffff, 0x7fffffff, 0x7fffffff, 0x7fffffff};
#pragma unroll 4
        for (int e = 0; e < 32; e++) {
            float v = sv[tid * 32 + e];
            int  ix = si[tid * 32 + e];
#pragma unroll
            for (int j = 0; j < 4; j++) {
                bool better = (v > v4[j]) || (v == v4[j] && ix < i4[j]);
                if (better) {
                    float tv = v4[j]; int ti = i4[j];
                    v4[j] = v; i4[j] = ix;
                    v = tv; ix = ti;
                }
            }
        }
        size_t base = (size_t)(m0 + tid) * 16 + (size_t)blockIdx.y * 4;
#pragma unroll
        for (int j = 0; j < 4; j++) g_cand[base + j] = i4[j];
    }
}

// ---------------------------------------------------------------------------
// Fused: exact fp64 re-check of 16 candidates + rep + reg_z gather.
// ---------------------------------------------------------------------------
__global__ void fixup_gather_kernel(const float* __restrict__ Z,
                                    const float* __restrict__ E,
                                    float* __restrict__ rep,
                                    float* __restrict__ regz)
{
    int row = (int)((blockIdx.x * (size_t)blockDim.x + threadIdx.x) >> 5);
    int lane = threadIdx.x & 31;
    if (row >= MT) return;
    int myc = (lane < 16) ? g_cand[(size_t)row * 16 + lane] : 0;
    const float* z = Z + (size_t)row * DB + lane * 8;
    float zc[8];
#pragma unroll
    for (int j = 0; j < 8; j++) zc[j] = z[j];
    double bd = 1.0e300; int bi = 0x7fffffff;
#pragma unroll 1
    for (int c = 0; c < 16; c++) {
        int idx = __shfl_sync(0xffffffffu, myc, c);
        const float* e = E + (size_t)idx * DB + lane * 8;
        double s = 0.0;
#pragma unroll
        for (int j = 0; j < 8; j++) {
            double d = (double)zc[j] - (double)e[j];
            s += d * d;
        }
#pragma unroll
        for (int off = 16; off > 0; off >>= 1)
            s += __shfl_xor_sync(0xffffffffu, s, off);
        if (s < bd || (s == bd && idx < bi)) { bd = s; bi = idx; }
    }
    if (lane == 0) rep[row] = (float)bi;

    const float4* e4 = (const float4*)(E + (size_t)bi * DB);
    float4 v0 = e4[lane];
    float4 v1 = e4[lane + 32];
    float4* r4 = (float4*)(regz + (size_t)row * DB);
    r4[lane] = v0;
    r4[lane + 32] = v1;
    uint2 h0, h1;
    h0.x = pack2h(v0.x, v0.y); h0.y = pack2h(v0.z, v0.w);
    h1.x = pack2h(v1.x, v1.y); h1.y = pack2h(v1.z, v1.w);
    uint2* rh = (uint2*)(g_rzh + (size_t)row * DB);
    rh[lane] = h0;
    rh[lane + 32] = h1;
}

// ---------------------------------------------------------------------------
// x_hat = reg_z @ W_out + b_out via f16 mma, f32 accumulate, staged cp.async.
// ---------------------------------------------------------------------------
__global__ __launch_bounds__(512, 1) void xhat_mma_kernel(
    const float* __restrict__ bias, float* __restrict__ C)
{
    extern __shared__ char smem[];
    const uint32_t sbase = smem_to_u32(smem);
    const uint32_t sA0 = sbase;
    const uint32_t sB0 = sbase + 2 * STAGE_B;

    const int tid  = threadIdx.x;
    const int lane = tid & 31;
    const int wid  = tid >> 5;
    const int warpM = (wid >> 2) * 32;
    const int warpN = (wid & 3) * 32;
    const int m0 = blockIdx.x * 128;
    const int n0 = blockIdx.y * 128;
    const int tg2 = (lane & 3) * 2;

#pragma unroll
    for (int s = 0; s < 2; s++) {
#pragma unroll
        for (int i = 0; i < 4; i++) {
            int ch = tid + i * 512;
            int row = ch >> 4, c = ch & 15;
            CP_ASYNC16(sA0 + s * STAGE_B + row * LDS2 + c * 16,
                       (const void*)(g_rzh + (size_t)(m0 + row) * DB + s * 128 + c * 8));
            CP_ASYNC16(sB0 + s * STAGE_B + row * LDS2 + c * 16,
                       (const void*)(g_wouth + (size_t)(n0 + row) * DB + s * 128 + c * 8));
        }
        CP_COMMIT();
    }

    float acc[2][4][4];
#pragma unroll
    for (int mi = 0; mi < 2; mi++)
#pragma unroll
        for (int ni = 0; ni < 4; ni++)
#pragma unroll
            for (int c = 0; c < 4; c++) acc[mi][ni][c] = 0.f;

#pragma unroll
    for (int s = 0; s < 2; s++) {
        if (s == 0) { CP_WAIT(1); } else { CP_WAIT(0); }
        __syncthreads();
        const uint32_t sA = sA0 + s * STAGE_B;
        const uint32_t sB = sB0 + s * STAGE_B;
#pragma unroll
        for (int k = 0; k < 8; k++) {
            uint32_t af[2][4], bfr[2][4];
#pragma unroll
            for (int mi = 0; mi < 2; mi++) {
                int row = warpM + mi * 16 + (lane & 15);
                int col = k * 16 + ((lane >> 4) << 3);
                ldsm_x4(af[mi], sA + row * LDS2 + col * 2);
            }
#pragma unroll
            for (int ni2 = 0; ni2 < 2; ni2++) {
                int row = warpN + ni2 * 16 + (lane & 7) + (((lane >> 4) & 1) << 3);
                int col = k * 16 + (((lane >> 3) & 1) << 3);
                ldsm_x4(bfr[ni2], sB + row * LDS2 + col * 2);
            }
#pragma unroll
            for (int mi = 0; mi < 2; mi++)
#pragma unroll
                for (int ni = 0; ni < 4; ni++)
                    mma16816_f(acc[mi][ni], af[mi], &bfr[ni >> 1][(ni & 1) * 2]);
        }
    }

#pragma unroll
    for (int mi = 0; mi < 2; mi++) {
#pragma unroll
        for (int h = 0; h < 2; h++) {
            int row = m0 + warpM + mi * 16 + (lane >> 2) + h * 8;
#pragma unroll
            for (int ni = 0; ni < 4; ni++) {
                int col = n0 + warpN + ni * 8 + tg2;
                float2 o;
                o.x = acc[mi][ni][h * 2 + 0] + __ldg(bias + col + 0);
                o.y = acc[mi][ni][h * 2 + 1] + __ldg(bias + col + 1);
                *(float2*)(C + (size_t)row * DIN + col) = o;
            }
        }
    }
}

// ---------------------------------------------------------------------------
extern "C" void kernel_launch(void* const* d_in, const int* in_sizes, int n_in,
                              void* d_out, int out_size)
{
    const float* x        = (const float*)d_in[0];
    const float* W_in     = (const float*)d_in[1];
    const float* b_in     = (const float*)d_in[2];
    const float* W_out    = (const float*)d_in[3];
    const float* b_out    = (const float*)d_in[4];
    const float* codebook = (const float*)d_in[5];
    const float* W_proj   = (const float*)d_in[6];
    const float* b_proj   = (const float*)d_in[7];

    float* out      = (float*)d_out;
    float* out_xhat = out;
    float* out_rep  = out_xhat + (size_t)MT * DIN;
    float* out_z    = out_rep + MT;
    float* out_emb  = out_z + (size_t)MT * DB;
    float* out_regz = out_emb + (size_t)KC * DB;

    cudaFuncSetAttribute(argmin_mma_kernel,
                         cudaFuncAttributeMaxDynamicSharedMemorySize, SMEM_ARG);
    cudaFuncSetAttribute(xhat_mma_kernel,
                         cudaFuncAttributeMaxDynamicSharedMemorySize, SMEM_XHAT);

    __half* zh; cudaGetSymbolAddress((void**)&zh, g_zh);
    __half* eh; cudaGetSymbolAddress((void**)&eh, g_eh);

    // 1) z = x @ W_in + b_in  (fp32 + fused fp16 mirror)
    gemm_bias_kernel<<<dim3(DB / 128, MT / 128), 256>>>(x, W_in, b_in, out_z, zh, DIN, DB);
    // 2) emb = codebook @ W_proj + b_proj  (fp32 + fused fp16 mirror)
    gemm_bias_kernel<<<dim3(DB / 128, KC / 128), 256>>>(codebook, W_proj, b_proj, out_emb, eh, DB, DB);
    // 3) half norms
    halfnorm_kernel<<<KC / 8, 256>>>(out_emb);
    // 4) W_out^T fp16
    convert_wout_kernel<<<(DB * DIN) / 256, 256>>>(W_out);
    // 5) hybrid HMMA + HFMA2 score GEMM + candidate tracking
    argmin_mma_kernel<<<dim3(MT / 128, NSPLIT), 512, SMEM_ARG>>>();
    // 6) fused exact fp64 re-check + rep + reg_z gather
    fixup_gather_kernel<<<(MT * 32) / 256, 256>>>(out_z, out_emb, out_rep, out_regz);
    // 7) x_hat = reg_z @ W_out + b_out (f16 mma, f32 accum)
    xhat_mma_kernel<<<dim3(MT / 128, DIN / 128), 512, SMEM_XHAT>>>(b_out, out_xhat);
}

// round 11
// speedup vs baseline: 1.6809x; 1.6809x over previous
#include <cuda_runtime.h>
#include <cuda_fp16.h>
#include <cstdint>

// Problem constants
#define MT     32768
#define DIN    1024
#define DB     256
#define KC     16384
#define NSPLIT 4
#define CODES_PER_SPLIT (KC / NSPLIT)   // 4096
#define NT_CTA (CODES_PER_SPLIT / 128)  // 32 tiles of 128 codes

#define LDA    264                       // padded f16 row stride (528 B)
#define A_F16  (128 * LDA * 2)           // 67584
#define SMEM_ARG  (3 * A_F16)            // 202752
#define SMEM_XHAT (2 * A_F16)            // 135168

// Scratch (__device__ globals; no allocation allowed)
__device__ float  g_halfnorm[KC];
__device__ int    g_qidx[MT];
__device__ int    g_cand[MT * 16];
__device__ __half g_zh[(size_t)MT * DB];
__device__ __half g_eh[(size_t)KC * DB];
__device__ __half g_rzh[(size_t)MT * DB];
__device__ __half g_wouth[(size_t)DIN * DB]; // W_out^T fp16 [N=1024, K=256]

// ======================= PTX helpers (baseline sm_80+) =====================
__device__ __forceinline__ uint32_t smem_to_u32(const void* p) {
    uint32_t a;
    asm("{ .reg .u64 t; cvta.to.shared.u64 t, %1; cvt.u32.u64 %0, t; }"
        : "=r"(a) : "l"(p));
    return a;
}
__device__ __forceinline__ void ldsm_x4(uint32_t* r, uint32_t addr) {
    asm volatile("ldmatrix.sync.aligned.m8n8.x4.shared.b16 {%0,%1,%2,%3}, [%4];"
                 : "=r"(r[0]), "=r"(r[1]), "=r"(r[2]), "=r"(r[3]) : "r"(addr));
}
// f16 accumulator (empirically exact-in-pool per R6-R10 rel_err equality)
__device__ __forceinline__ void mma16816_h(uint32_t* c, const uint32_t* a,
                                           const uint32_t* b) {
    asm volatile(
        "mma.sync.aligned.m16n8k16.row.col.f16.f16.f16.f16 "
        "{%0,%1}, {%2,%3,%4,%5}, {%6,%7}, {%0,%1};"
        : "+r"(c[0]), "+r"(c[1])
        : "r"(a[0]), "r"(a[1]), "r"(a[2]), "r"(a[3]), "r"(b[0]), "r"(b[1]));
}
// f32 accumulator, f16 inputs (x_hat GEMM)
__device__ __forceinline__ void mma16816_f(float* c, const uint32_t* a,
                                           const uint32_t* b) {
    asm volatile(
        "mma.sync.aligned.m16n8k16.row.col.f32.f16.f16.f32 "
        "{%0,%1,%2,%3}, {%4,%5,%6,%7}, {%8,%9}, {%0,%1,%2,%3};"
        : "+f"(c[0]), "+f"(c[1]), "+f"(c[2]), "+f"(c[3])
        : "r"(a[0]), "r"(a[1]), "r"(a[2]), "r"(a[3]), "r"(b[0]), "r"(b[1]));
}
#define CP_ASYNC16(dst, src) \
    asm volatile("cp.async.cg.shared.global [%0], [%1], 16;" :: "r"(dst), "l"(src))
#define CP_COMMIT()  asm volatile("cp.async.commit_group;" ::: "memory")
#define CP_WAIT(n)   asm volatile("cp.async.wait_group %0;" :: "n"(n) : "memory")

__device__ __forceinline__ uint32_t pack2h(float a, float b)
{
    return ((uint32_t)__half_as_ushort(__float2half_rn(b)) << 16) |
           (uint32_t)__half_as_ushort(__float2half_rn(a));
}

// ---------------------------------------------------------------------------
// fp32 GEMM with bias, register-buffered K pipeline, optional fp16 mirror.
// ---------------------------------------------------------------------------
__global__ __launch_bounds__(256, 2) void gemm_bias_kernel(
    const float* __restrict__ A, const float* __restrict__ B,
    const float* __restrict__ bias, float* __restrict__ C,
    __half* __restrict__ Ch, int Kd, int N)
{
    __shared__ float As[8][128];
    __shared__ float Bs[8][128];
    const int rowBase = blockIdx.y * 128;
    const int colBase = blockIdx.x * 128;
    const int tid = threadIdx.x;
    const int ty = tid >> 4, tx = tid & 15;

    float acc[8][8];
#pragma unroll
    for (int i = 0; i < 8; i++)
#pragma unroll
        for (int j = 0; j < 8; j++) acc[i][j] = 0.f;

    const int ar = tid >> 1, ac4 = (tid & 1) * 4;
    const int br = tid >> 5, bc = (tid & 31) * 4;
    const float* Aptr = A + (size_t)(rowBase + ar) * Kd + ac4;
    const float* Bptr = B + (size_t)br * N + colBase + bc;

    float4 av = *(const float4*)(Aptr);
    float4 bv = *(const float4*)(Bptr);

    for (int kt = 0; kt < Kd; kt += 8) {
        As[ac4 + 0][ar] = av.x; As[ac4 + 1][ar] = av.y;
        As[ac4 + 2][ar] = av.z; As[ac4 + 3][ar] = av.w;
        *(float4*)(&Bs[br][bc]) = bv;
        __syncthreads();
        if (kt + 8 < Kd) {
            av = *(const float4*)(Aptr + kt + 8);
            bv = *(const float4*)(Bptr + (size_t)(kt + 8) * N);
        }
#pragma unroll
        for (int k = 0; k < 8; k++) {
            float4 a0 = *(const float4*)(&As[k][ty * 8]);
            float4 a1 = *(const float4*)(&As[k][ty * 8 + 4]);
            float4 b0 = *(const float4*)(&Bs[k][tx * 8]);
            float4 b1 = *(const float4*)(&Bs[k][tx * 8 + 4]);
            float ra[8] = {a0.x, a0.y, a0.z, a0.w, a1.x, a1.y, a1.z, a1.w};
            float rb[8] = {b0.x, b0.y, b0.z, b0.w, b1.x, b1.y, b1.z, b1.w};
#pragma unroll
            for (int i = 0; i < 8; i++)
#pragma unroll
                for (int j = 0; j < 8; j++) acc[i][j] += ra[i] * rb[j];
        }
        __syncthreads();
    }
#pragma unroll
    for (int i = 0; i < 8; i++) {
        int row = rowBase + ty * 8 + i;
#pragma unroll
        for (int j = 0; j < 8; j += 4) {
            int col = colBase + tx * 8 + j;
            float4 o;
            o.x = acc[i][j + 0] + __ldg(bias + col + 0);
            o.y = acc[i][j + 1] + __ldg(bias + col + 1);
            o.z = acc[i][j + 2] + __ldg(bias + col + 2);
            o.w = acc[i][j + 3] + __ldg(bias + col + 3);
            *(float4*)(C + (size_t)row * N + col) = o;
            if (Ch) {
                uint2 h;
                h.x = pack2h(o.x, o.y);
                h.y = pack2h(o.z, o.w);
                *(uint2*)(Ch + (size_t)row * N + col) = h;
            }
        }
    }
}

// ---------------------------------------------------------------------------
__global__ void halfnorm_kernel(const float* __restrict__ E)
{
    int row = blockIdx.x * 8 + (threadIdx.x >> 5);
    int lane = threadIdx.x & 31;
    const float* e = E + (size_t)row * DB;
    float s = 0.f;
#pragma unroll
    for (int c = lane; c < DB; c += 32) { float v = e[c]; s += v * v; }
#pragma unroll
    for (int off = 16; off > 0; off >>= 1) s += __shfl_xor_sync(0xffffffffu, s, off);
    if (lane == 0) g_halfnorm[row] = 0.5f * s;
}

// W_out [K=256, N=1024] fp32 -> W_out^T [N=1024, K=256] fp16
__global__ void convert_wout_kernel(const float* __restrict__ W)
{
    int idx = blockIdx.x * 256 + threadIdx.x;
    int k = idx >> 10, n = idx & 1023;
    g_wouth[(size_t)n * DB + k] = __float2half_rn(W[idx]);
}

// ---------------------------------------------------------------------------
// Fused f16 mma (f16 accumulate) score GEMM + per-row candidate tracking.
// Grid (MT/128, NSPLIT), 512 threads (16 warps: 4(M) x 4(N), warp tile 32x32).
// ---------------------------------------------------------------------------
__global__ __launch_bounds__(512, 1) void argmin_mma_kernel()
{
    extern __shared__ char smem[];
    const uint32_t sbase = smem_to_u32(smem);
    const uint32_t sA  = sbase;
    const uint32_t sB0 = sbase + A_F16;

    const int tid  = threadIdx.x;
    const int lane = tid & 31;
    const int wid  = tid >> 5;
    const int wm   = wid >> 2;
    const int wn   = wid & 3;
    const int warpM = wm * 32;
    const int warpN = wn * 32;
    const int m0 = blockIdx.x * 128;
    const int codeBase = blockIdx.y * CODES_PER_SPLIT;
    const int tg2 = (lane & 3) * 2;

    // ---- A panel -> smem ----
#pragma unroll
    for (int i = 0; i < 8; i++) {
        int ch = tid + i * 512;
        int row = ch >> 5, c = ch & 31;
        uint4 v = *(const uint4*)(g_zh + (size_t)(m0 + row) * DB + c * 8);
        *(uint4*)(smem + row * (LDA * 2) + c * 16) = v;
    }

    // ---- prologue: B tile 0 ----
    {
        const __half* src0 = g_eh + (size_t)codeBase * DB;
#pragma unroll
        for (int i = 0; i < 8; i++) {
            int ch = tid + i * 512;
            int row = ch >> 5, c = ch & 31;
            CP_ASYNC16(sB0 + row * (LDA * 2) + c * 16,
                       (const void*)(src0 + (size_t)row * DB + c * 8));
        }
        CP_COMMIT();
    }

    float b1v[4], b2v[4];
    int   b1i[4], b2i[4];
#pragma unroll
    for (int s = 0; s < 4; s++) {
        b1v[s] = -3.4e38f; b2v[s] = -3.4e38f; b1i[s] = 0; b2i[s] = 0;
    }

    for (int t = 0; t < NT_CTA; t++) {
        const int buf = t & 1;
        const uint32_t sBcur = sB0 + buf * A_F16;
        if (t + 1 < NT_CTA) {
            const uint32_t sBnext = sB0 + (buf ^ 1) * A_F16;
            const __half* src0 = g_eh + (size_t)(codeBase + (t + 1) * 128) * DB;
#pragma unroll
            for (int i = 0; i < 8; i++) {
                int ch = tid + i * 512;
                int row = ch >> 5, c = ch & 31;
                CP_ASYNC16(sBnext + row * (LDA * 2) + c * 16,
                           (const void*)(src0 + (size_t)row * DB + c * 8));
            }
            CP_COMMIT();
            CP_WAIT(1);
        } else {
            CP_WAIT(0);
        }
        __syncthreads();

        // ---- compute 128x128 tile (warp 32x32), f16 accumulate ----
        uint32_t acc[2][4][2];
#pragma unroll
        for (int mi = 0; mi < 2; mi++)
#pragma unroll
            for (int ni = 0; ni < 4; ni++) { acc[mi][ni][0] = 0u; acc[mi][ni][1] = 0u; }

#pragma unroll
        for (int k = 0; k < 16; k++) {
            uint32_t af[2][4], bfr[2][4];
#pragma unroll
            for (int mi = 0; mi < 2; mi++) {
                int row = warpM + mi * 16 + (lane & 15);
                int col = k * 16 + ((lane >> 4) << 3);
                ldsm_x4(af[mi], sA + row * (LDA * 2) + col * 2);
            }
#pragma unroll
            for (int ni2 = 0; ni2 < 2; ni2++) {
                int row = warpN + ni2 * 16 + (lane & 7) + (((lane >> 4) & 1) << 3);
                int col = k * 16 + (((lane >> 3) & 1) << 3);
                ldsm_x4(bfr[ni2], sBcur + row * (LDA * 2) + col * 2);
            }
#pragma unroll
            for (int mi = 0; mi < 2; mi++)
#pragma unroll
                for (int ni = 0; ni < 4; ni++)
                    mma16816_h(acc[mi][ni], af[mi], &bfr[ni >> 1][(ni & 1) * 2]);
        }
        __syncthreads();

        // ---- fold into per-slot top-2 ----
        const int nb = codeBase + t * 128 + warpN;
        float hn[4][2];
#pragma unroll
        for (int ni = 0; ni < 4; ni++) {
            int code = nb + ni * 8 + tg2;
            hn[ni][0] = __ldg(&g_halfnorm[code]);
            hn[ni][1] = __ldg(&g_halfnorm[code + 1]);
        }
#pragma unroll
        for (int mi = 0; mi < 2; mi++) {
#pragma unroll
            for (int h = 0; h < 2; h++) {
                const int s = mi * 2 + h;
                float vv[8];
#pragma unroll
                for (int ni = 0; ni < 4; ni++) {
                    float2 f = __half22float2(*(__half2*)&acc[mi][ni][h]);
                    vv[ni * 2 + 0] = f.x - hn[ni][0];
                    vv[ni * 2 + 1] = f.y - hn[ni][1];
                }
                float m01 = fmaxf(vv[0], vv[1]), m23 = fmaxf(vv[2], vv[3]);
                float m45 = fmaxf(vv[4], vv[5]), m67 = fmaxf(vv[6], vv[7]);
                float mx = fmaxf(fmaxf(m01, m23), fmaxf(m45, m67));
                if (mx > b2v[s]) {
#pragma unroll
                    for (int e = 0; e < 8; e++) {
                        float v = vv[e];
                        int code = nb + (e >> 1) * 8 + tg2 + (e & 1);
                        if (v > b1v[s]) {
                            b2v[s] = b1v[s]; b2i[s] = b1i[s];
                            b1v[s] = v;      b1i[s] = code;
                        } else if (v > b2v[s]) {
                            b2v[s] = v; b2i[s] = code;
                        }
                    }
                }
            }
        }
    }

    // ---- per-CTA reduction: 32 candidates/row -> top-4 codes ----
    __syncthreads();
    float* sv = (float*)smem;
    int*   si = (int*)(smem + 16384);
#pragma unroll
    for (int s = 0; s < 4; s++) {
        int row = warpM + (s >> 1) * 16 + (s & 1) * 8 + (lane >> 2);
        int e = wn * 8 + (lane & 3) * 2;
        sv[row * 32 + e]     = b1v[s]; si[row * 32 + e]     = b1i[s];
        sv[row * 32 + e + 1] = b2v[s]; si[row * 32 + e + 1] = b2i[s];
    }
    __syncthreads();
    if (tid < 128) {
        float v4[4] = {-3.4e38f, -3.4e38f, -3.4e38f, -3.4e38f};
        int   i4[4] = {0x7fffffff, 0x7fffffff, 0x7fffffff, 0x7fffffff};
#pragma unroll 4
        for (int e = 0; e < 32; e++) {
            float v = sv[tid * 32 + e];
            int  ix = si[tid * 32 + e];
#pragma unroll
            for (int j = 0; j < 4; j++) {
                bool better = (v > v4[j]) || (v == v4[j] && ix < i4[j]);
                if (better) {
                    float tv = v4[j]; int ti = i4[j];
                    v4[j] = v; i4[j] = ix;
                    v = tv; ix = ti;
                }
            }
        }
        size_t base = (size_t)(m0 + tid) * 16 + (size_t)blockIdx.y * 4;
#pragma unroll
        for (int j = 0; j < 4; j++) g_cand[base + j] = i4[j];
    }
}

// ---------------------------------------------------------------------------
// Exact fp64 re-check of the 16 candidates per row (1 warp / row).
// ---------------------------------------------------------------------------
__global__ void fixup_kernel(const float* __restrict__ Z, const float* __restrict__ E,
                             float* __restrict__ rep)
{
    int row = (int)((blockIdx.x * (size_t)blockDim.x + threadIdx.x) >> 5);
    int lane = threadIdx.x & 31;
    if (row >= MT) return;
    int myc = (lane < 16) ? g_cand[(size_t)row * 16 + lane] : 0;
    const float* z = Z + (size_t)row * DB + lane * 8;
    float zc[8];
#pragma unroll
    for (int j = 0; j < 8; j++) zc[j] = z[j];
    double bd = 1.0e300; int bi = 0x7fffffff;
#pragma unroll 1
    for (int c = 0; c < 16; c++) {
        int idx = __shfl_sync(0xffffffffu, myc, c);
        const float* e = E + (size_t)idx * DB + lane * 8;
        double s = 0.0;
#pragma unroll
        for (int j = 0; j < 8; j++) {
            double d = (double)zc[j] - (double)e[j];
            s += d * d;
        }
#pragma unroll
        for (int off = 16; off > 0; off >>= 1)
            s += __shfl_xor_sync(0xffffffffu, s, off);
        if (s < bd || (s == bd && idx < bi)) { bd = s; bi = idx; }
    }
    if (lane == 0) {
        g_qidx[row] = bi;
        rep[row] = (float)bi;
    }
}

// ---------------------------------------------------------------------------
// gather: reg_z fp32 output block + fp16 copy for the x_hat mma GEMM
// ---------------------------------------------------------------------------
__global__ void gather_kernel(const float* __restrict__ E, float* __restrict__ regz)
{
    size_t t = (size_t)blockIdx.x * blockDim.x + threadIdx.x;
    int r = (int)(t >> 6);
    int c4 = (int)(t & 63) << 2;
    int idx = g_qidx[r];
    float4 v = *(const float4*)(E + (size_t)idx * DB + c4);
    *(float4*)(regz + (size_t)r * DB + c4) = v;
    uint2 h;
    h.x = pack2h(v.x, v.y);
    h.y = pack2h(v.z, v.w);
    *(uint2*)(g_rzh + (size_t)r * DB + c4) = h;
}

// ---------------------------------------------------------------------------
// x_hat = reg_z @ W_out + b_out via f16 mma, f32 accumulate.
// ---------------------------------------------------------------------------
__global__ __launch_bounds__(512, 1) void xhat_mma_kernel(
    const float* __restrict__ bias, float* __restrict__ C)
{
    extern __shared__ char smem[];
    const uint32_t sbase = smem_to_u32(smem);
    const uint32_t sA = sbase;
    const uint32_t sB = sbase + A_F16;

    const int tid  = threadIdx.x;
    const int lane = tid & 31;
    const int wid  = tid >> 5;
    const int warpM = (wid >> 2) * 32;
    const int warpN = (wid & 3) * 32;
    const int m0 = blockIdx.x * 128;
    const int n0 = blockIdx.y * 128;
    const int tg2 = (lane & 3) * 2;

#pragma unroll
    for (int i = 0; i < 8; i++) {
        int ch = tid + i * 512;
        int row = ch >> 5, c = ch & 31;
        uint4 va = *(const uint4*)(g_rzh + (size_t)(m0 + row) * DB + c * 8);
        *(uint4*)(smem + row * (LDA * 2) + c * 16) = va;
        uint4 vb = *(const uint4*)(g_wouth + (size_t)(n0 + row) * DB + c * 8);
        *(uint4*)(smem + A_F16 + row * (LDA * 2) + c * 16) = vb;
    }
    __syncthreads();

    float acc[2][4][4];
#pragma unroll
    for (int mi = 0; mi < 2; mi++)
#pragma unroll
        for (int ni = 0; ni < 4; ni++)
#pragma unroll
            for (int c = 0; c < 4; c++) acc[mi][ni][c] = 0.f;

#pragma unroll
    for (int k = 0; k < 16; k++) {
        uint32_t af[2][4], bfr[2][4];
#pragma unroll
        for (int mi = 0; mi < 2; mi++) {
            int row = warpM + mi * 16 + (lane & 15);
            int col = k * 16 + ((lane >> 4) << 3);
            ldsm_x4(af[mi], sA + row * (LDA * 2) + col * 2);
        }
#pragma unroll
        for (int ni2 = 0; ni2 < 2; ni2++) {
            int row = warpN + ni2 * 16 + (lane & 7) + (((lane >> 4) & 1) << 3);
            int col = k * 16 + (((lane >> 3) & 1) << 3);
            ldsm_x4(bfr[ni2], sB + row * (LDA * 2) + col * 2);
        }
#pragma unroll
        for (int mi = 0; mi < 2; mi++)
#pragma unroll
            for (int ni = 0; ni < 4; ni++)
                mma16816_f(acc[mi][ni], af[mi], &bfr[ni >> 1][(ni & 1) * 2]);
    }

#pragma unroll
    for (int mi = 0; mi < 2; mi++) {
#pragma unroll
        for (int h = 0; h < 2; h++) {
            int row = m0 + warpM + mi * 16 + (lane >> 2) + h * 8;
#pragma unroll
            for (int ni = 0; ni < 4; ni++) {
                int col = n0 + warpN + ni * 8 + tg2;
                float2 o;
                o.x = acc[mi][ni][h * 2 + 0] + __ldg(bias + col + 0);
                o.y = acc[mi][ni][h * 2 + 1] + __ldg(bias + col + 1);
                *(float2*)(C + (size_t)row * DIN + col) = o;
            }
        }
    }
}

// ---------------------------------------------------------------------------
extern "C" void kernel_launch(void* const* d_in, const int* in_sizes, int n_in,
                              void* d_out, int out_size)
{
    const float* x        = (const float*)d_in[0];
    const float* W_in     = (const float*)d_in[1];
    const float* b_in     = (const float*)d_in[2];
    const float* W_out    = (const float*)d_in[3];
    const float* b_out    = (const float*)d_in[4];
    const float* codebook = (const float*)d_in[5];
    const float* W_proj   = (const float*)d_in[6];
    const float* b_proj   = (const float*)d_in[7];

    float* out      = (float*)d_out;
    float* out_xhat = out;
    float* out_rep  = out_xhat + (size_t)MT * DIN;
    float* out_z    = out_rep + MT;
    float* out_emb  = out_z + (size_t)MT * DB;
    float* out_regz = out_emb + (size_t)KC * DB;

    cudaFuncSetAttribute(argmin_mma_kernel,
                         cudaFuncAttributeMaxDynamicSharedMemorySize, SMEM_ARG);
    cudaFuncSetAttribute(xhat_mma_kernel,
                         cudaFuncAttributeMaxDynamicSharedMemorySize, SMEM_XHAT);

    __half* zh; cudaGetSymbolAddress((void**)&zh, g_zh);
    __half* eh; cudaGetSymbolAddress((void**)&eh, g_eh);

    // Fork a side branch for the emb/halfnorm/wout chain so it overlaps the
    // larger z-gemm. Events/stream are created fresh each call (this host code
    // runs only during the correctness call and the single capture call; graph
    // replays execute the recorded nodes only). Kernel launches only — capture
    // safe via the standard event fork/join pattern.
    cudaStream_t s2;
    cudaEvent_t eFork, eJoin;
    cudaStreamCreateWithFlags(&s2, cudaStreamNonBlocking);
    cudaEventCreateWithFlags(&eFork, cudaEventDisableTiming);
    cudaEventCreateWithFlags(&eJoin, cudaEventDisableTiming);

    cudaEventRecord(eFork, 0);
    cudaStreamWaitEvent(s2, eFork, 0);

    // main branch: 1) z = x @ W_in + b_in  (fp32 + fused fp16 mirror)
    gemm_bias_kernel<<<dim3(DB / 128, MT / 128), 256>>>(x, W_in, b_in, out_z, zh, DIN, DB);

    // side branch: 2) emb gemm  3) half norms  4) W_out^T fp16
    gemm_bias_kernel<<<dim3(DB / 128, KC / 128), 256, 0, s2>>>(codebook, W_proj, b_proj,
                                                               out_emb, eh, DB, DB);
    halfnorm_kernel<<<KC / 8, 256, 0, s2>>>(out_emb);
    convert_wout_kernel<<<(DB * DIN) / 256, 256, 0, s2>>>(W_out);

    cudaEventRecord(eJoin, s2);
    cudaStreamWaitEvent(0, eJoin, 0);

    // 5) fused f16-accum mma score GEMM + candidate tracking
    argmin_mma_kernel<<<dim3(MT / 128, NSPLIT), 512, SMEM_ARG>>>();
    // 6) exact fp64 candidate re-check -> q_idx, bottleneck_rep
    fixup_kernel<<<(MT * 32) / 256, 256>>>(out_z, out_emb, out_rep);
    // 7) reg_z = emb[q_idx]  (fp32 output + fp16 copy)
    gather_kernel<<<(MT * 64) / 256, 256>>>(out_emb, out_regz);
    // 8) x_hat = reg_z @ W_out + b_out (f16 mma, f32 accum)
    xhat_mma_kernel<<<dim3(MT / 128, DIN / 128), 512, SMEM_XHAT>>>(b_out, out_xhat);
}

// round 13
// speedup vs baseline: 1.7040x; 1.0138x over previous
#include <cuda_runtime.h>
#include <cuda_fp16.h>
#include <cstdint>

// Problem constants
#define MT     32768
#define MH     (MT / 2)                  // rows per pipeline half
#define DIN    1024
#define DB     256
#define KC     16384
#define NSPLIT 4
#define CODES_PER_SPLIT (KC / NSPLIT)   // 4096
#define NT_CTA (CODES_PER_SPLIT / 128)  // 32 tiles of 128 codes

#define LDA    264                       // padded f16 row stride (528 B)
#define A_F16  (128 * LDA * 2)           // 67584
#define SMEM_ARG  (3 * A_F16)            // 202752
#define SMEM_XHAT (2 * A_F16)            // 135168

// Scratch (__device__ globals; no allocation allowed)
__device__ float  g_halfnorm[KC];
__device__ int    g_cand[MT * 16];
__device__ __half g_zh[(size_t)MT * DB];
__device__ __half g_eh[(size_t)KC * DB];
__device__ __half g_rzh[(size_t)MT * DB];
__device__ __half g_wouth[(size_t)DIN * DB]; // W_out^T fp16 [N=1024, K=256]

// ======================= PTX helpers (baseline sm_80+) =====================
__device__ __forceinline__ uint32_t smem_to_u32(const void* p) {
    uint32_t a;
    asm("{ .reg .u64 t; cvta.to.shared.u64 t, %1; cvt.u32.u64 %0, t; }"
        : "=r"(a) : "l"(p));
    return a;
}
__device__ __forceinline__ void ldsm_x4(uint32_t* r, uint32_t addr) {
    asm volatile("ldmatrix.sync.aligned.m8n8.x4.shared.b16 {%0,%1,%2,%3}, [%4];"
                 : "=r"(r[0]), "=r"(r[1]), "=r"(r[2]), "=r"(r[3]) : "r"(addr));
}
// f16 accumulator (empirically exact-in-pool per R6-R12 rel_err equality)
__device__ __forceinline__ void mma16816_h(uint32_t* c, const uint32_t* a,
                                           const uint32_t* b) {
    asm volatile(
        "mma.sync.aligned.m16n8k16.row.col.f16.f16.f16.f16 "
        "{%0,%1}, {%2,%3,%4,%5}, {%6,%7}, {%0,%1};"
        : "+r"(c[0]), "+r"(c[1])
        : "r"(a[0]), "r"(a[1]), "r"(a[2]), "r"(a[3]), "r"(b[0]), "r"(b[1]));
}
// f32 accumulator, f16 inputs (x_hat GEMM)
__device__ __forceinline__ void mma16816_f(float* c, const uint32_t* a,
                                           const uint32_t* b) {
    asm volatile(
        "mma.sync.aligned.m16n8k16.row.col.f32.f16.f16.f32 "
        "{%0,%1,%2,%3}, {%4,%5,%6,%7}, {%8,%9}, {%0,%1,%2,%3};"
        : "+f"(c[0]), "+f"(c[1]), "+f"(c[2]), "+f"(c[3])
        : "r"(a[0]), "r"(a[1]), "r"(a[2]), "r"(a[3]), "r"(b[0]), "r"(b[1]));
}
#define CP_ASYNC16(dst, src) \
    asm volatile("cp.async.cg.shared.global [%0], [%1], 16;" :: "r"(dst), "l"(src))
#define CP_COMMIT()  asm volatile("cp.async.commit_group;" ::: "memory")
#define CP_WAIT(n)   asm volatile("cp.async.wait_group %0;" :: "n"(n) : "memory")

__device__ __forceinline__ uint32_t pack2h(float a, float b)
{
    return ((uint32_t)__half_as_ushort(__float2half_rn(b)) << 16) |
           (uint32_t)__half_as_ushort(__float2half_rn(a));
}

// ---------------------------------------------------------------------------
// fp32 GEMM with bias, register-buffered K pipeline, optional fp16 mirror.
// ---------------------------------------------------------------------------
__global__ __launch_bounds__(256, 2) void gemm_bias_kernel(
    const float* __restrict__ A, const float* __restrict__ B,
    const float* __restrict__ bias, float* __restrict__ C,
    __half* __restrict__ Ch, int Kd, int N)
{
    __shared__ float As[8][128];
    __shared__ float Bs[8][128];
    const int rowBase = blockIdx.y * 128;
    const int colBase = blockIdx.x * 128;
    const int tid = threadIdx.x;
    const int ty = tid >> 4, tx = tid & 15;

    float acc[8][8];
#pragma unroll
    for (int i = 0; i < 8; i++)
#pragma unroll
        for (int j = 0; j < 8; j++) acc[i][j] = 0.f;

    const int ar = tid >> 1, ac4 = (tid & 1) * 4;
    const int br = tid >> 5, bc = (tid & 31) * 4;
    const float* Aptr = A + (size_t)(rowBase + ar) * Kd + ac4;
    const float* Bptr = B + (size_t)br * N + colBase + bc;

    float4 av = *(const float4*)(Aptr);
    float4 bv = *(const float4*)(Bptr);

    for (int kt = 0; kt < Kd; kt += 8) {
        As[ac4 + 0][ar] = av.x; As[ac4 + 1][ar] = av.y;
        As[ac4 + 2][ar] = av.z; As[ac4 + 3][ar] = av.w;
        *(float4*)(&Bs[br][bc]) = bv;
        __syncthreads();
        if (kt + 8 < Kd) {
            av = *(const float4*)(Aptr + kt + 8);
            bv = *(const float4*)(Bptr + (size_t)(kt + 8) * N);
        }
#pragma unroll
        for (int k = 0; k < 8; k++) {
            float4 a0 = *(const float4*)(&As[k][ty * 8]);
            float4 a1 = *(const float4*)(&As[k][ty * 8 + 4]);
            float4 b0 = *(const float4*)(&Bs[k][tx * 8]);
            float4 b1 = *(const float4*)(&Bs[k][tx * 8 + 4]);
            float ra[8] = {a0.x, a0.y, a0.z, a0.w, a1.x, a1.y, a1.z, a1.w};
            float rb[8] = {b0.x, b0.y, b0.z, b0.w, b1.x, b1.y, b1.z, b1.w};
#pragma unroll
            for (int i = 0; i < 8; i++)
#pragma unroll
                for (int j = 0; j < 8; j++) acc[i][j] += ra[i] * rb[j];
        }
        __syncthreads();
    }
#pragma unroll
    for (int i = 0; i < 8; i++) {
        int row = rowBase + ty * 8 + i;
#pragma unroll
        for (int j = 0; j < 8; j += 4) {
            int col = colBase + tx * 8 + j;
            float4 o;
            o.x = acc[i][j + 0] + __ldg(bias + col + 0);
            o.y = acc[i][j + 1] + __ldg(bias + col + 1);
            o.z = acc[i][j + 2] + __ldg(bias + col + 2);
            o.w = acc[i][j + 3] + __ldg(bias + col + 3);
            *(float4*)(C + (size_t)row * N + col) = o;
            if (Ch) {
                uint2 h;
                h.x = pack2h(o.x, o.y);
                h.y = pack2h(o.z, o.w);
                *(uint2*)(Ch + (size_t)row * N + col) = h;
            }
        }
    }
}

// ---------------------------------------------------------------------------
__global__ void halfnorm_kernel(const float* __restrict__ E)
{
    int row = blockIdx.x * 8 + (threadIdx.x >> 5);
    int lane = threadIdx.x & 31;
    const float* e = E + (size_t)row * DB;
    float s = 0.f;
#pragma unroll
    for (int c = lane; c < DB; c += 32) { float v = e[c]; s += v * v; }
#pragma unroll
    for (int off = 16; off > 0; off >>= 1) s += __shfl_xor_sync(0xffffffffu, s, off);
    if (lane == 0) g_halfnorm[row] = 0.5f * s;
}

// W_out [K=256, N=1024] fp32 -> W_out^T [N=1024, K=256] fp16
__global__ void convert_wout_kernel(const float* __restrict__ W)
{
    int idx = blockIdx.x * 256 + threadIdx.x;
    int k = idx >> 10, n = idx & 1023;
    g_wouth[(size_t)n * DB + k] = __float2half_rn(W[idx]);
}

// ---------------------------------------------------------------------------
// Fused f16 mma (f16 accumulate) score GEMM + per-row candidate tracking.
// Grid (MH/128, NSPLIT) per half, 512 threads; mOff selects the row half.
// ---------------------------------------------------------------------------
__global__ __launch_bounds__(512, 1) void argmin_mma_kernel(int mOff)
{
    extern __shared__ char smem[];
    const uint32_t sbase = smem_to_u32(smem);
    const uint32_t sA  = sbase;
    const uint32_t sB0 = sbase + A_F16;

    const int tid  = threadIdx.x;
    const int lane = tid & 31;
    const int wid  = tid >> 5;
    const int wm   = wid >> 2;
    const int wn   = wid & 3;
    const int warpM = wm * 32;
    const int warpN = wn * 32;
    const int m0 = mOff + blockIdx.x * 128;
    const int codeBase = blockIdx.y * CODES_PER_SPLIT;
    const int tg2 = (lane & 3) * 2;

    // ---- A panel -> smem ----
#pragma unroll
    for (int i = 0; i < 8; i++) {
        int ch = tid + i * 512;
        int row = ch >> 5, c = ch & 31;
        uint4 v = *(const uint4*)(g_zh + (size_t)(m0 + row) * DB + c * 8);
        *(uint4*)(smem + row * (LDA * 2) + c * 16) = v;
    }

    // ---- prologue: B tile 0 ----
    {
        const __half* src0 = g_eh + (size_t)codeBase * DB;
#pragma unroll
        for (int i = 0; i < 8; i++) {
            int ch = tid + i * 512;
            int row = ch >> 5, c = ch & 31;
            CP_ASYNC16(sB0 + row * (LDA * 2) + c * 16,
                       (const void*)(src0 + (size_t)row * DB + c * 8));
        }
        CP_COMMIT();
    }

    float b1v[4], b2v[4];
    int   b1i[4], b2i[4];
#pragma unroll
    for (int s = 0; s < 4; s++) {
        b1v[s] = -3.4e38f; b2v[s] = -3.4e38f; b1i[s] = 0; b2i[s] = 0;
    }

    for (int t = 0; t < NT_CTA; t++) {
        const int buf = t & 1;
        const uint32_t sBcur = sB0 + buf * A_F16;
        if (t + 1 < NT_CTA) {
            const uint32_t sBnext = sB0 + (buf ^ 1) * A_F16;
            const __half* src0 = g_eh + (size_t)(codeBase + (t + 1) * 128) * DB;
#pragma unroll
            for (int i = 0; i < 8; i++) {
                int ch = tid + i * 512;
                int row = ch >> 5, c = ch & 31;
                CP_ASYNC16(sBnext + row * (LDA * 2) + c * 16,
                           (const void*)(src0 + (size_t)row * DB + c * 8));
            }
            CP_COMMIT();
            CP_WAIT(1);
        } else {
            CP_WAIT(0);
        }
        __syncthreads();

        // ---- compute 128x128 tile (warp 32x32), f16 accumulate ----
        uint32_t acc[2][4][2];
#pragma unroll
        for (int mi = 0; mi < 2; mi++)
#pragma unroll
            for (int ni = 0; ni < 4; ni++) { acc[mi][ni][0] = 0u; acc[mi][ni][1] = 0u; }

#pragma unroll
        for (int k = 0; k < 16; k++) {
            uint32_t af[2][4], bfr[2][4];
#pragma unroll
            for (int mi = 0; mi < 2; mi++) {
                int row = warpM + mi * 16 + (lane & 15);
                int col = k * 16 + ((lane >> 4) << 3);
                ldsm_x4(af[mi], sA + row * (LDA * 2) + col * 2);
            }
#pragma unroll
            for (int ni2 = 0; ni2 < 2; ni2++) {
                int row = warpN + ni2 * 16 + (lane & 7) + (((lane >> 4) & 1) << 3);
                int col = k * 16 + (((lane >> 3) & 1) << 3);
                ldsm_x4(bfr[ni2], sBcur + row * (LDA * 2) + col * 2);
            }
#pragma unroll
            for (int mi = 0; mi < 2; mi++)
#pragma unroll
                for (int ni = 0; ni < 4; ni++)
                    mma16816_h(acc[mi][ni], af[mi], &bfr[ni >> 1][(ni & 1) * 2]);
        }
        __syncthreads();

        // ---- fold into per-slot top-2 ----
        const int nb = codeBase + t * 128 + warpN;
        float hn[4][2];
#pragma unroll
        for (int ni = 0; ni < 4; ni++) {
            int code = nb + ni * 8 + tg2;
            hn[ni][0] = __ldg(&g_halfnorm[code]);
            hn[ni][1] = __ldg(&g_halfnorm[code + 1]);
        }
#pragma unroll
        for (int mi = 0; mi < 2; mi++) {
#pragma unroll
            for (int h = 0; h < 2; h++) {
                const int s = mi * 2 + h;
                float vv[8];
#pragma unroll
                for (int ni = 0; ni < 4; ni++) {
                    float2 f = __half22float2(*(__half2*)&acc[mi][ni][h]);
                    vv[ni * 2 + 0] = f.x - hn[ni][0];
                    vv[ni * 2 + 1] = f.y - hn[ni][1];
                }
                float m01 = fmaxf(vv[0], vv[1]), m23 = fmaxf(vv[2], vv[3]);
                float m45 = fmaxf(vv[4], vv[5]), m67 = fmaxf(vv[6], vv[7]);
                float mx = fmaxf(fmaxf(m01, m23), fmaxf(m45, m67));
                if (mx > b2v[s]) {
#pragma unroll
                    for (int e = 0; e < 8; e++) {
                        float v = vv[e];
                        int code = nb + (e >> 1) * 8 + tg2 + (e & 1);
                        if (v > b1v[s]) {
                            b2v[s] = b1v[s]; b2i[s] = b1i[s];
                            b1v[s] = v;      b1i[s] = code;
                        } else if (v > b2v[s]) {
                            b2v[s] = v; b2i[s] = code;
                        }
                    }
                }
            }
        }
    }

    // ---- per-CTA reduction: 32 candidates/row -> top-4 codes ----
    __syncthreads();
    float* sv = (float*)smem;
    int*   si = (int*)(smem + 16384);
#pragma unroll
    for (int s = 0; s < 4; s++) {
        int row = warpM + (s >> 1) * 16 + (s & 1) * 8 + (lane >> 2);
        int e = wn * 8 + (lane & 3) * 2;
        sv[row * 32 + e]     = b1v[s]; si[row * 32 + e]     = b1i[s];
        sv[row * 32 + e + 1] = b2v[s]; si[row * 32 + e + 1] = b2i[s];
    }
    __syncthreads();
    if (tid < 128) {
        float v4[4] = {-3.4e38f, -3.4e38f, -3.4e38f, -3.4e38f};
        int   i4[4] = {0x7fffffff, 0x7fffffff, 0x7fffffff, 0x7fffffff};
#pragma unroll 4
        for (int e = 0; e < 32; e++) {
            float v = sv[tid * 32 + e];
            int  ix = si[tid * 32 + e];
#pragma unroll
            for (int j = 0; j < 4; j++) {
                bool better = (v > v4[j]) || (v == v4[j] && ix < i4[j]);
                if (better) {
                    float tv = v4[j]; int ti = i4[j];
                    v4[j] = v; i4[j] = ix;
                    v = tv; ix = ti;
                }
            }
        }
        size_t base = (size_t)(m0 + tid) * 16 + (size_t)blockIdx.y * 4;
#pragma unroll
        for (int j = 0; j < 4; j++) g_cand[base + j] = i4[j];
    }
}

// ---------------------------------------------------------------------------
// Fused: exact fp64 re-check of 16 candidates + rep + reg_z gather
// (fp32 output block + fp16 mirror). 1 warp / row; rowOff selects the half.
// ---------------------------------------------------------------------------
__global__ void fixup_gather_kernel(const float* __restrict__ Z,
                                    const float* __restrict__ E,
                                    float* __restrict__ rep,
                                    float* __restrict__ regz,
                                    int rowOff)
{
    int row = rowOff + (int)((blockIdx.x * (size_t)blockDim.x + threadIdx.x) >> 5);
    int lane = threadIdx.x & 31;
    int myc = (lane < 16) ? g_cand[(size_t)row * 16 + lane] : 0;
    const float* z = Z + (size_t)row * DB + lane * 8;
    float zc[8];
#pragma unroll
    for (int j = 0; j < 8; j++) zc[j] = z[j];
    double bd = 1.0e300; int bi = 0x7fffffff;
#pragma unroll 1
    for (int c = 0; c < 16; c++) {
        int idx = __shfl_sync(0xffffffffu, myc, c);
        const float* e = E + (size_t)idx * DB + lane * 8;
        double s = 0.0;
#pragma unroll
        for (int j = 0; j < 8; j++) {
            double d = (double)zc[j] - (double)e[j];
            s += d * d;
        }
#pragma unroll
        for (int off = 16; off > 0; off >>= 1)
            s += __shfl_xor_sync(0xffffffffu, s, off);
        // s uniform across lanes after butterfly -> bd/bi uniform
        if (s < bd || (s == bd && idx < bi)) { bd = s; bi = idx; }
    }
    if (lane == 0) rep[row] = (float)bi;

    const float4* e4 = (const float4*)(E + (size_t)bi * DB);
    float4 v0 = e4[lane];
    float4 v1 = e4[lane + 32];
    float4* r4 = (float4*)(regz + (size_t)row * DB);
    r4[lane] = v0;
    r4[lane + 32] = v1;
    uint2 h0, h1;
    h0.x = pack2h(v0.x, v0.y); h0.y = pack2h(v0.z, v0.w);
    h1.x = pack2h(v1.x, v1.y); h1.y = pack2h(v1.z, v1.w);
    uint2* rh = (uint2*)(g_rzh + (size_t)row * DB);
    rh[lane] = h0;
    rh[lane + 32] = h1;
}

// ---------------------------------------------------------------------------
// x_hat = reg_z @ W_out + b_out via f16 mma, f32 accumulate. mOff = row half.
// ---------------------------------------------------------------------------
__global__ __launch_bounds__(512, 1) void xhat_mma_kernel(
    const float* __restrict__ bias, float* __restrict__ C, int mOff)
{
    extern __shared__ char smem[];
    const uint32_t sbase = smem_to_u32(smem);
    const uint32_t sA = sbase;
    const uint32_t sB = sbase + A_F16;

    const int tid  = threadIdx.x;
    const int lane = tid & 31;
    const int wid  = tid >> 5;
    const int warpM = (wid >> 2) * 32;
    const int warpN = (wid & 3) * 32;
    const int m0 = mOff + blockIdx.x * 128;
    const int n0 = blockIdx.y * 128;
    const int tg2 = (lane & 3) * 2;

#pragma unroll
    for (int i = 0; i < 8; i++) {
        int ch = tid + i * 512;
        int row = ch >> 5, c = ch & 31;
        uint4 va = *(const uint4*)(g_rzh + (size_t)(m0 + row) * DB + c * 8);
        *(uint4*)(smem + row * (LDA * 2) + c * 16) = va;
        uint4 vb = *(const uint4*)(g_wouth + (size_t)(n0 + row) * DB + c * 8);
        *(uint4*)(smem + A_F16 + row * (LDA * 2) + c * 16) = vb;
    }
    __syncthreads();

    float acc[2][4][4];
#pragma unroll
    for (int mi = 0; mi < 2; mi++)
#pragma unroll
        for (int ni = 0; ni < 4; ni++)
#pragma unroll
            for (int c = 0; c < 4; c++) acc[mi][ni][c] = 0.f;

#pragma unroll
    for (int k = 0; k < 16; k++) {
        uint32_t af[2][4], bfr[2][4];
#pragma unroll
        for (int mi = 0; mi < 2; mi++) {
            int row = warpM + mi * 16 + (lane & 15);
            int col = k * 16 + ((lane >> 4) << 3);
            ldsm_x4(af[mi], sA + row * (LDA * 2) + col * 2);
        }
#pragma unroll
        for (int ni2 = 0; ni2 < 2; ni2++) {
            int row = warpN + ni2 * 16 + (lane & 7) + (((lane >> 4) & 1) << 3);
            int col = k * 16 + (((lane >> 3) & 1) << 3);
            ldsm_x4(bfr[ni2], sB + row * (LDA * 2) + col * 2);
        }
#pragma unroll
        for (int mi = 0; mi < 2; mi++)
#pragma unroll
            for (int ni = 0; ni < 4; ni++)
                mma16816_f(acc[mi][ni], af[mi], &bfr[ni >> 1][(ni & 1) * 2]);
    }

#pragma unroll
    for (int mi = 0; mi < 2; mi++) {
#pragma unroll
        for (int h = 0; h < 2; h++) {
            int row = m0 + warpM + mi * 16 + (lane >> 2) + h * 8;
#pragma unroll
            for (int ni = 0; ni < 4; ni++) {
                int col = n0 + warpN + ni * 8 + tg2;
                float2 o;
                o.x = acc[mi][ni][h * 2 + 0] + __ldg(bias + col + 0);
                o.y = acc[mi][ni][h * 2 + 1] + __ldg(bias + col + 1);
                *(float2*)(C + (size_t)row * DIN + col) = o;
            }
        }
    }
}

// ---------------------------------------------------------------------------
extern "C" void kernel_launch(void* const* d_in, const int* in_sizes, int n_in,
                              void* d_out, int out_size)
{
    const float* x        = (const float*)d_in[0];
    const float* W_in     = (const float*)d_in[1];
    const float* b_in     = (const float*)d_in[2];
    const float* W_out    = (const float*)d_in[3];
    const float* b_out    = (const float*)d_in[4];
    const float* codebook = (const float*)d_in[5];
    const float* W_proj   = (const float*)d_in[6];
    const float* b_proj   = (const float*)d_in[7];

    float* out      = (float*)d_out;
    float* out_xhat = out;
    float* out_rep  = out_xhat + (size_t)MT * DIN;
    float* out_z    = out_rep + MT;
    float* out_emb  = out_z + (size_t)MT * DB;
    float* out_regz = out_emb + (size_t)KC * DB;

    cudaFuncSetAttribute(argmin_mma_kernel,
                         cudaFuncAttributeMaxDynamicSharedMemorySize, SMEM_ARG);
    cudaFuncSetAttribute(xhat_mma_kernel,
                         cudaFuncAttributeMaxDynamicSharedMemorySize, SMEM_XHAT);

    __half* zh; cudaGetSymbolAddress((void**)&zh, g_zh);
    __half* eh; cudaGetSymbolAddress((void**)&eh, g_eh);

    // ONE extra stream only (R11-proven passing config; a second stream grows
    // the driver stream pool by 2 MB and trips the teardown memory check).
    cudaStream_t s2;
    cudaEvent_t eFork, eJoin, eJoin2, eEnd;
    cudaStreamCreateWithFlags(&s2, cudaStreamNonBlocking);
    cudaEventCreateWithFlags(&eFork, cudaEventDisableTiming);
    cudaEventCreateWithFlags(&eJoin, cudaEventDisableTiming);
    cudaEventCreateWithFlags(&eJoin2, cudaEventDisableTiming);
    cudaEventCreateWithFlags(&eEnd, cudaEventDisableTiming);

    // ---- preamble fork: side chain overlaps z-gemm (proven in R11) ----
    cudaEventRecord(eFork, 0);
    cudaStreamWaitEvent(s2, eFork, 0);

    gemm_bias_kernel<<<dim3(DB / 128, MT / 128), 256>>>(x, W_in, b_in, out_z, zh, DIN, DB);

    gemm_bias_kernel<<<dim3(DB / 128, KC / 128), 256, 0, s2>>>(codebook, W_proj, b_proj,
                                                               out_emb, eh, DB, DB);
    halfnorm_kernel<<<KC / 8, 256, 0, s2>>>(out_emb);
    convert_wout_kernel<<<(DB * DIN) / 256, 256, 0, s2>>>(W_out);

    // join side chain into main, then carry the combined dependency back to s2
    cudaEventRecord(eJoin, s2);
    cudaStreamWaitEvent(0, eJoin, 0);
    cudaEventRecord(eJoin2, 0);
    cudaStreamWaitEvent(s2, eJoin2, 0);

    // ---- half-pipelined argmin -> fixup_gather -> xhat ----
    // Half 0 on main (enqueued first -> drains first); half 1 on s2.
    argmin_mma_kernel<<<dim3(MH / 128, NSPLIT), 512, SMEM_ARG>>>(0);
    argmin_mma_kernel<<<dim3(MH / 128, NSPLIT), 512, SMEM_ARG, s2>>>(MH);

    // Half-0 tail chain (overlaps argmin half 1 on s2).
    fixup_gather_kernel<<<(MH * 32) / 256, 256>>>(out_z, out_emb, out_rep, out_regz, 0);
    xhat_mma_kernel<<<dim3(MH / 128, DIN / 128), 512, SMEM_XHAT>>>(b_out, out_xhat, 0);

    // Half-1 tail chain on s2.
    fixup_gather_kernel<<<(MH * 32) / 256, 256, 0, s2>>>(out_z, out_emb, out_rep, out_regz, MH);
    xhat_mma_kernel<<<dim3(MH / 128, DIN / 128), 512, SMEM_XHAT, s2>>>(b_out, out_xhat, MH);

    // Rejoin before capture ends.
    cudaEventRecord(eEnd, s2);
    cudaStreamWaitEvent(0, eEnd, 0);
}